// round 1
// baseline (speedup 1.0000x reference)
#include <cuda_runtime.h>
#include <math.h>

// MonotonicSpline: y[i] = cubic uniform B-spline(x[i]) with monotone coef vector.
//
// coef[0] = c0; coef[j] = c0 + sum_{i<j} (MIN + (MAX-MIN)*sigmoid(raw_delta[i]))
// Uniform knots t_k = (k-3)*h, h = 1/40. Only 4 cubic basis funcs are nonzero
// per x; closed-form uniform cubic B-spline weights replace the de Boor
// recursion (EPS=1e-8 in reference denominators is ~4e-7 relative -> far
// below the 1e-3 tolerance; x/(1+1e-8) == x in fp32).

static constexpr int   NUM_KNOTS = 40;
static constexpr float MIN_DELTA = 0.5f / NUM_KNOTS;
static constexpr float MAX_DELTA = 3.0f / NUM_KNOTS;
static constexpr int   THREADS   = 256;

__device__ __forceinline__ float eval_spline(float xv, const float* __restrict__ sc) {
    // clip to [0,1] (x/(1+eps) is identity in fp32)
    float xn = fminf(fmaxf(xv, 0.0f), 1.0f);
    float t  = xn * (float)NUM_KNOTS;
    int   idx = (int)t;                 // floor, t >= 0
    idx = min(idx, NUM_KNOTS - 1);      // x == 1.0 edge
    float u  = t - (float)idx;
    float u2 = u * u;
    float u3 = u2 * u;
    float om = 1.0f - u;
    const float s = 1.0f / 6.0f;
    float w0 = s * om * om * om;
    float w1 = s * (3.0f * u3 - 6.0f * u2 + 4.0f);
    float w2 = s * (-3.0f * u3 + 3.0f * u2 + 3.0f * u + 1.0f);
    float w3 = s * u3;
    return w0 * sc[idx] + w1 * sc[idx + 1] + w2 * sc[idx + 2] + w3 * sc[idx + 3];
}

__global__ void __launch_bounds__(THREADS)
monotonic_spline_kernel(const float* __restrict__ x,
                        const float* __restrict__ c0,
                        const float* __restrict__ raw_delta,
                        float* __restrict__ y,
                        int n4, int n) {
    __shared__ float partial[43];   // inclusive per-warp scans of deltas
    __shared__ float sc[43];        // final coef vector

    const int tid = threadIdx.x;

    // ---- per-block coef computation (warps 0 and 1 only) ----
    if (tid < 64) {
        float d = 0.0f;
        if (tid < 42) {
            float r = raw_delta[tid];
            d = MIN_DELTA + (MAX_DELTA - MIN_DELTA) / (1.0f + expf(-r));
        }
        // warp-level inclusive scan (warps 0 and 1 are fully active)
        #pragma unroll
        for (int off = 1; off < 32; off <<= 1) {
            float tsh = __shfl_up_sync(0xffffffffu, d, off);
            if ((tid & 31) >= off) d += tsh;
        }
        if (tid < 42) partial[tid + 1] = d;
    }
    __syncthreads();
    if (tid < 43) {
        float c0v = __ldg(c0);
        float v;
        if (tid == 0)        v = c0v;
        else if (tid <= 32)  v = c0v + partial[tid];
        else                 v = c0v + partial[32] + partial[tid];
        sc[tid] = v;
    }
    __syncthreads();

    // ---- vectorized streaming evaluation ----
    const int i = blockIdx.x * THREADS + tid;
    if (i < n4) {
        const float4 v = reinterpret_cast<const float4*>(x)[i];
        float4 o;
        o.x = eval_spline(v.x, sc);
        o.y = eval_spline(v.y, sc);
        o.z = eval_spline(v.z, sc);
        o.w = eval_spline(v.w, sc);
        reinterpret_cast<float4*>(y)[i] = o;
    }

    // scalar tail (n not divisible by 4) — handled by the first few threads
    // of block 0
    if (blockIdx.x == 0) {
        int base = n4 * 4;
        int j = base + tid;
        if (j < n) y[j] = eval_spline(x[j], sc);
    }
}

extern "C" void kernel_launch(void* const* d_in, const int* in_sizes, int n_in,
                              void* d_out, int out_size) {
    const float* x         = (const float*)d_in[0];
    // d_in[1] = grid (uniform, values implied by construction; unused)
    const float* c0        = (const float*)d_in[2];
    const float* raw_delta = (const float*)d_in[3];
    float* y = (float*)d_out;

    int n  = in_sizes[0];
    int n4 = n / 4;
    int blocks = (n4 + THREADS - 1) / THREADS;
    if (blocks == 0) blocks = 1;

    monotonic_spline_kernel<<<blocks, THREADS>>>(x, c0, raw_delta, y, n4, n);
}

// round 2
// speedup vs baseline: 1.1130x; 1.1130x over previous
#include <cuda_runtime.h>
#include <math.h>

// MonotonicSpline: y[i] = cubic uniform B-spline(clip(x[i],0,1)).
// coef[0]=c0; coef[j]=c0 + sum_{i<j}(MIN+(MAX-MIN)*sigmoid(raw_delta[i])).
// Uniform knots h=1/40 -> only 4 basis funcs nonzero; further reduced to a
// per-segment cubic polynomial y = ((a*u+b)*u+c)*u+d with u = frac(40*x):
//   a=(c3-c0+3(c1-c2))/6, b=(c0-2c1+c2)/2, c=(c2-c0)/2, d=(c0+4c1+c2)/6.
// (EPS=1e-8 reference fudge is ~4e-7 relative; x/(1+1e-8)==x in fp32.)

static constexpr int   NUM_KNOTS = 40;
static constexpr float MIN_DELTA = 0.5f / NUM_KNOTS;
static constexpr float MAX_DELTA = 3.0f / NUM_KNOTS;
static constexpr int   THREADS   = 256;
static constexpr int   ITEMS     = 4;     // float4s per thread

__device__ float4 g_poly[NUM_KNOTS];      // per-segment (d,c,b,a)

// ---------------- prep: coefs -> per-segment poly (1 block) ----------------
__global__ void prep_kernel(const float* __restrict__ c0,
                            const float* __restrict__ raw_delta) {
    __shared__ float coef[NUM_KNOTS + 3];   // 43
    const int tid = threadIdx.x;   // 64 threads

    float d = 0.0f;
    if (tid < 42) {
        float r = raw_delta[tid];
        d = MIN_DELTA + (MAX_DELTA - MIN_DELTA) / (1.0f + expf(-r));
    }
    // inclusive scan across 2 full warps
    #pragma unroll
    for (int off = 1; off < 32; off <<= 1) {
        float t = __shfl_up_sync(0xffffffffu, d, off);
        if ((tid & 31) >= off) d += t;
    }
    __shared__ float warp0_total;
    if (tid == 31) warp0_total = d;
    __shared__ float scan[43];
    if (tid < 42) scan[tid + 1] = d;
    __syncthreads();
    if (tid < 43) {
        float c0v = *c0;
        float v = c0v;
        if (tid >= 1)  v += scan[tid] + ((tid > 32) ? warp0_total : 0.0f);
        coef[tid] = v;
    }
    __syncthreads();
    if (tid < NUM_KNOTS) {
        float p0 = coef[tid], p1 = coef[tid + 1], p2 = coef[tid + 2], p3 = coef[tid + 3];
        float4 o;
        o.x = (p0 + 4.0f * p1 + p2) * (1.0f / 6.0f);              // d (u^0)
        o.y = (p2 - p0) * 0.5f;                                   // c (u^1)
        o.z = (p0 - 2.0f * p1 + p2) * 0.5f;                       // b (u^2)
        o.w = (p3 - p0 + 3.0f * (p1 - p2)) * (1.0f / 6.0f);       // a (u^3)
        g_poly[tid] = o;
    }
}

// ---------------- main streaming eval ----------------
__device__ __forceinline__ float eval_one(float xv, const float4* __restrict__ rep,
                                          int lane8) {
    float xn = fminf(fmaxf(xv, 0.0f), 1.0f);
    float t  = xn * (float)NUM_KNOTS;
    int   idx = min((int)t, NUM_KNOTS - 1);
    float u  = t - (float)idx;
    float4 p = rep[idx * 8 + lane8];        // conflict-free LDS.128
    return ((p.w * u + p.z) * u + p.y) * u + p.x;
}

__global__ void __launch_bounds__(THREADS)
spline_eval_kernel(const float* __restrict__ x,
                   float* __restrict__ y,
                   int n4, int n) {
    __shared__ float4 rep[NUM_KNOTS * 8];   // 8-way bank-replicated table, 5120 B

    const int tid = threadIdx.x;
    // fill replicated table: rep[j*8 + r] = g_poly[j]
    #pragma unroll
    for (int e = tid; e < NUM_KNOTS * 8; e += THREADS)
        rep[e] = g_poly[e >> 3];
    __syncthreads();

    const int lane8 = tid & 7;
    const float4* __restrict__ x4 = reinterpret_cast<const float4*>(x);
    float4* __restrict__ y4 = reinterpret_cast<float4*>(y);

    int base = blockIdx.x * (THREADS * ITEMS) + tid;
    #pragma unroll
    for (int it = 0; it < ITEMS; ++it) {
        int i = base + it * THREADS;
        if (i < n4) {
            float4 v = x4[i];
            float4 o;
            o.x = eval_one(v.x, rep, lane8);
            o.y = eval_one(v.y, rep, lane8);
            o.z = eval_one(v.z, rep, lane8);
            o.w = eval_one(v.w, rep, lane8);
            y4[i] = o;
        }
    }

    // scalar tail (n % 4 != 0) — block 0 only
    if (blockIdx.x == 0) {
        int j = n4 * 4 + tid;
        if (j < n) y[j] = eval_one(x[j], rep, lane8);
    }
}

extern "C" void kernel_launch(void* const* d_in, const int* in_sizes, int n_in,
                              void* d_out, int out_size) {
    const float* x         = (const float*)d_in[0];
    // d_in[1] = grid (uniform; values implied by construction)
    const float* c0        = (const float*)d_in[2];
    const float* raw_delta = (const float*)d_in[3];
    float* y = (float*)d_out;

    int n  = in_sizes[0];
    int n4 = n / 4;

    prep_kernel<<<1, 64>>>(c0, raw_delta);

    int per_block = THREADS * ITEMS;
    int blocks = (n4 + per_block - 1) / per_block;
    if (blocks == 0) blocks = 1;
    spline_eval_kernel<<<blocks, THREADS>>>(x, y, n4, n);
}

// round 3
// speedup vs baseline: 1.1963x; 1.0748x over previous
#include <cuda_runtime.h>
#include <math.h>

// MonotonicSpline: y[i] = cubic uniform B-spline(clip(x[i],0,1)).
// coef[0]=c0; coef[j]=c0 + sum_{i<j}(MIN+(MAX-MIN)*sigmoid(raw_delta[i])).
// Uniform knots h=1/40 -> per-segment cubic y = ((a*u+b)*u+c)*u+d, u=frac(40x):
//   d=(c0+4c1+c2)/6, c=(c2-c0)/2, b=(c0-2c1+c2)/2, a=(c3-c0+3(c1-c2))/6.
// Single fused kernel: each block rebuilds the 40-entry poly table (cheap
// prologue) into an 8-way bank-replicated smem table, then streams 8 float4
// per thread with batched loads for MLP.

static constexpr int   NUM_KNOTS = 40;
static constexpr float MIN_DELTA = 0.5f / NUM_KNOTS;
static constexpr float MAX_DELTA = 3.0f / NUM_KNOTS;
static constexpr int   THREADS   = 256;
static constexpr int   ITEMS     = 8;     // float4s per thread

__device__ __forceinline__ float eval_one(float xv, const float4* __restrict__ rep,
                                          int lane8) {
    float t   = xv * (float)NUM_KNOTS;
    int   idx = __float2int_rz(t);
    idx = max(0, min(idx, NUM_KNOTS - 1));
    float u   = __saturatef(t - (float)idx);      // FADD.SAT: clamps x<0 / x>=1
    float4 p  = rep[idx * 8 + lane8];             // conflict-free LDS.128
    return ((p.w * u + p.z) * u + p.y) * u + p.x;
}

__global__ void __launch_bounds__(THREADS)
spline_fused_kernel(const float* __restrict__ x,
                    const float* __restrict__ c0,
                    const float* __restrict__ raw_delta,
                    float* __restrict__ y,
                    int n4, int n) {
    __shared__ float  scan[43];
    __shared__ float  warp0_total;
    __shared__ float  coef[43];
    __shared__ float4 rep[NUM_KNOTS * 8];   // 8-way replicated poly table, 5 KB

    const int tid = threadIdx.x;

    // ---- prologue: deltas -> cumsum -> poly table (warps 0-1 scan) ----
    if (tid < 64) {
        float d = 0.0f;
        if (tid < 42) {
            float r = raw_delta[tid];
            d = MIN_DELTA + (MAX_DELTA - MIN_DELTA) / (1.0f + __expf(-r));
        }
        #pragma unroll
        for (int off = 1; off < 32; off <<= 1) {
            float t = __shfl_up_sync(0xffffffffu, d, off);
            if ((tid & 31) >= off) d += t;
        }
        if (tid == 31) warp0_total = d;
        if (tid < 42) scan[tid + 1] = d;
    }
    __syncthreads();
    if (tid < 43) {
        float v = __ldg(c0);
        if (tid >= 1) v += scan[tid] + ((tid > 32) ? warp0_total : 0.0f);
        coef[tid] = v;
    }
    __syncthreads();
    #pragma unroll
    for (int e = tid; e < NUM_KNOTS * 8; e += THREADS) {
        int j = e >> 3;
        float p0 = coef[j], p1 = coef[j + 1], p2 = coef[j + 2], p3 = coef[j + 3];
        float4 o;
        o.x = (p0 + 4.0f * p1 + p2) * (1.0f / 6.0f);
        o.y = (p2 - p0) * 0.5f;
        o.z = (p0 - 2.0f * p1 + p2) * 0.5f;
        o.w = (p3 - p0 + 3.0f * (p1 - p2)) * (1.0f / 6.0f);
        rep[e] = o;
    }
    __syncthreads();

    // ---- streaming eval: batch all loads first (MLP), then compute+store ----
    const int lane8 = tid & 7;
    const float4* __restrict__ x4 = reinterpret_cast<const float4*>(x);
    float4* __restrict__ y4 = reinterpret_cast<float4*>(y);
    const int base = blockIdx.x * (THREADS * ITEMS) + tid;

    float4 v[ITEMS];
    #pragma unroll
    for (int it = 0; it < ITEMS; ++it) {
        int i = base + it * THREADS;
        if (i < n4) v[it] = x4[i];
    }
    #pragma unroll
    for (int it = 0; it < ITEMS; ++it) {
        int i = base + it * THREADS;
        if (i < n4) {
            float4 o;
            o.x = eval_one(v[it].x, rep, lane8);
            o.y = eval_one(v[it].y, rep, lane8);
            o.z = eval_one(v[it].z, rep, lane8);
            o.w = eval_one(v[it].w, rep, lane8);
            y4[i] = o;
        }
    }

    // scalar tail (n % 4 != 0) — block 0 only
    if (blockIdx.x == 0) {
        int j = n4 * 4 + tid;
        if (j < n) y[j] = eval_one(x[j], rep, lane8);
    }
}

extern "C" void kernel_launch(void* const* d_in, const int* in_sizes, int n_in,
                              void* d_out, int out_size) {
    const float* x         = (const float*)d_in[0];
    // d_in[1] = grid (uniform; values implied by construction)
    const float* c0        = (const float*)d_in[2];
    const float* raw_delta = (const float*)d_in[3];
    float* y = (float*)d_out;

    int n  = in_sizes[0];
    int n4 = n / 4;

    int per_block = THREADS * ITEMS;
    int blocks = (n4 + per_block - 1) / per_block;
    if (blocks == 0) blocks = 1;

    spline_fused_kernel<<<blocks, THREADS>>>(x, c0, raw_delta, y, n4, n);
}